// round 7
// baseline (speedup 1.0000x reference)
#include <cuda_runtime.h>

// Idx2PixelLayer bilinear gather — two-pass image-half partitioning for L2
// residency. Pass p processes only points whose base row i0 is in half p
// (i0 < 1024 for p=0). Within a pass the gather working set is 64MB < L2
// (126MB), so repeat sector-touches (37% of gather traffic) become L2 hits.
// Per-pass structure = R4 winner: 4 lanes/point, 2 points/lane-group, MLP 4.

#define HW 2048
#define CCH 8

__device__ __forceinline__ float4 ldg_stream4(const float* p) {
    float4 v;
    asm volatile("ld.global.cs.v4.f32 {%0,%1,%2,%3}, [%4];"
                 : "=f"(v.x), "=f"(v.y), "=f"(v.z), "=f"(v.w) : "l"(p));
    return v;
}

__device__ __forceinline__ void stg_stream4(float* p, float4 v) {
    asm volatile("st.global.cs.v4.f32 [%0], {%1,%2,%3,%4};"
                 :: "l"(p), "f"(v.x), "f"(v.y), "f"(v.z), "f"(v.w) : "memory");
}

__global__ __launch_bounds__(256) void idx2pixel_half_kernel(
    const float* __restrict__ coords,
    const float* __restrict__ vis,
    float* __restrict__ out,
    int n, int pass)
{
    int gtid  = blockIdx.x * blockDim.x + threadIdx.x;
    int w     = gtid >> 5;            // global warp id
    int lane  = threadIdx.x & 31;
    int group = lane >> 2;            // 0..7
    int j     = lane & 3;             // 0..3 within group
    int pbase = (w * 8 + group) * 2;  // first of the point pair
    if (pbase >= n) return;

    unsigned mask = __activemask();
    const float M = (float)(HW - 4);   // 2044

    // Two points' coords in one 16B load: (x0, y0, x1, y1)
    float4 cxy = ldg_stream4(coords + (size_t)pbase * 2);

    float c0a = fmodf(cxy.x - 1.0f, M); if (c0a < 0.0f) c0a += M; c0a += 1.0f;
    float c1a = fmodf(cxy.y - 1.0f, M); if (c1a < 0.0f) c1a += M; c1a += 1.0f;
    float c0b = fmodf(cxy.z - 1.0f, M); if (c0b < 0.0f) c0b += M; c0b += 1.0f;
    float c1b = fmodf(cxy.w - 1.0f, M); if (c1b < 0.0f) c1b += M; c1b += 1.0f;

    float f0a = floorf(c0a), f1a = floorf(c1a);
    float f0b = floorf(c0b), f1b = floorf(c1b);
    float d0a = c0a - f0a, d1a = c1a - f1a;
    float d0b = c0b - f0b, d1b = c1b - f1b;
    int i0a = (int)f0a, i1a = (int)f1a;
    int i0b = (int)f0b, i1b = (int)f1b;

    // half membership: i0 in [1, 2044]; (i0 >> 10) in {0, 1}
    bool actA = ((i0a >> 10) == pass);
    bool actB = ((i0b >> 10) == pass) && (pbase + 1 < n);

    const float* pa0 = vis + ((size_t)i0a * HW + i1a) * CCH + j * 4;
    const float* pa1 = pa0 + (size_t)HW * CCH;
    const float* pb0 = vis + ((size_t)i0b * HW + i1b) * CCH + j * 4;
    const float* pb1 = pb0 + (size_t)HW * CCH;

    float4 Aa = make_float4(0.f,0.f,0.f,0.f), Ba = Aa, Ab = Aa, Bb = Aa;
    if (actA) {
        Aa = __ldg(reinterpret_cast<const float4*>(pa0));  // tl/bl half
        Ba = __ldg(reinterpret_cast<const float4*>(pa1));  // tr/br half
    }
    if (actB) {
        Ab = __ldg(reinterpret_cast<const float4*>(pb0));
        Bb = __ldg(reinterpret_cast<const float4*>(pb1));
    }

    // v = B + d0*(A-B): lanes 0,1 -> mt ; lanes 2,3 -> mb
    float4 va, vb;
    va.x = Ba.x + d0a * (Aa.x - Ba.x);
    va.y = Ba.y + d0a * (Aa.y - Ba.y);
    va.z = Ba.z + d0a * (Aa.z - Ba.z);
    va.w = Ba.w + d0a * (Aa.w - Ba.w);
    vb.x = Bb.x + d0b * (Ab.x - Bb.x);
    vb.y = Bb.y + d0b * (Ab.y - Bb.y);
    vb.z = Bb.z + d0b * (Ab.z - Bb.z);
    vb.w = Bb.w + d0b * (Ab.w - Bb.w);

    float4 oa, ob;
    oa.x = __shfl_xor_sync(mask, va.x, 2);
    oa.y = __shfl_xor_sync(mask, va.y, 2);
    oa.z = __shfl_xor_sync(mask, va.z, 2);
    oa.w = __shfl_xor_sync(mask, va.w, 2);
    ob.x = __shfl_xor_sync(mask, vb.x, 2);
    ob.y = __shfl_xor_sync(mask, vb.y, 2);
    ob.z = __shfl_xor_sync(mask, vb.z, 2);
    ob.w = __shfl_xor_sync(mask, vb.w, 2);

    float4 mta, mba, mtb, mbb;
    if (j < 2) { mta = va; mba = oa; mtb = vb; mbb = ob; }
    else       { mta = oa; mba = va; mtb = ob; mbb = vb; }

    float4 ra, rb;
    ra.x = mba.x + d1a * (mta.x - mba.x);
    ra.y = mba.y + d1a * (mta.y - mba.y);
    ra.z = mba.z + d1a * (mta.z - mba.z);
    ra.w = mba.w + d1a * (mta.w - mba.w);
    rb.x = mbb.x + d1b * (mtb.x - mbb.x);
    rb.y = mbb.y + d1b * (mtb.y - mbb.y);
    rb.z = mbb.z + d1b * (mtb.z - mbb.z);
    rb.w = mbb.w + d1b * (mtb.w - mbb.w);

    // off = c > 2048 never true (c in [1, 2045)): no zeroing.
    if (j < 2) {
        if (actA) stg_stream4(out + ((size_t)pbase * CCH) + j * 4, ra);
        if (actB) stg_stream4(out + ((size_t)(pbase + 1) * CCH) + j * 4, rb);
    }
}

extern "C" void kernel_launch(void* const* d_in, const int* in_sizes, int n_in,
                              void* d_out, int out_size)
{
    const float* coords = (const float*)d_in[0];
    const float* vis    = (const float*)d_in[1];
    float* out          = (float*)d_out;

    int n = in_sizes[0] / 2;             // number of points
    int threads = 256;                    // 8 warps -> 128 points/block
    int ppb = (threads / 32) * 8 * 2;
    int blocks = (n + ppb - 1) / ppb;
    idx2pixel_half_kernel<<<blocks, threads>>>(coords, vis, out, n, 0);
    idx2pixel_half_kernel<<<blocks, threads>>>(coords, vis, out, n, 1);
}

// round 8
// speedup vs baseline: 1.3580x; 1.3580x over previous
#include <cuda_runtime.h>

// Idx2PixelLayer bilinear gather — single pass, asymmetric L2 pinning.
// Points with i0 < 1024 (lower half of visible, 64MB < L2 126MB) gather with
// evict_last -> that half stays L2-resident and its repeat sector-touches
// (~37%) hit. Points in the upper half gather with evict_first (streaming,
// minimal pollution of the pinned class). Structure = R4 winner:
// 4 lanes/point, 2 points/lane-group, MLP 4 gathers/thread.

#define HW 2048
#define CCH 8

__device__ __forceinline__ unsigned long long mk_policy_el() {
    unsigned long long p;
    asm("createpolicy.fractional.L2::evict_last.b64 %0, 1.0;" : "=l"(p));
    return p;
}
__device__ __forceinline__ unsigned long long mk_policy_ef() {
    unsigned long long p;
    asm("createpolicy.fractional.L2::evict_first.b64 %0, 1.0;" : "=l"(p));
    return p;
}

__device__ __forceinline__ float4 ldg_vis(const float* p, unsigned long long pol) {
    float4 v;
    asm volatile("ld.global.nc.L2::cache_hint.v4.f32 {%0,%1,%2,%3}, [%4], %5;"
                 : "=f"(v.x), "=f"(v.y), "=f"(v.z), "=f"(v.w)
                 : "l"(p), "l"(pol));
    return v;
}

__device__ __forceinline__ float4 ldg_stream4(const float* p) {
    float4 v;
    asm volatile("ld.global.cs.v4.f32 {%0,%1,%2,%3}, [%4];"
                 : "=f"(v.x), "=f"(v.y), "=f"(v.z), "=f"(v.w) : "l"(p));
    return v;
}

__device__ __forceinline__ void stg_stream4(float* p, float4 v) {
    asm volatile("st.global.cs.v4.f32 [%0], {%1,%2,%3,%4};"
                 :: "l"(p), "f"(v.x), "f"(v.y), "f"(v.z), "f"(v.w) : "memory");
}

__global__ __launch_bounds__(256) void idx2pixel_pin_kernel(
    const float* __restrict__ coords,
    const float* __restrict__ vis,
    float* __restrict__ out,
    int n)
{
    int gtid  = blockIdx.x * blockDim.x + threadIdx.x;
    int w     = gtid >> 5;            // global warp id
    int lane  = threadIdx.x & 31;
    int group = lane >> 2;            // 0..7
    int j     = lane & 3;             // 0..3 within group
    int pbase = (w * 8 + group) * 2;  // first of the point pair
    if (pbase >= n) return;

    unsigned mask = __activemask();
    unsigned long long pol_el = mk_policy_el();
    unsigned long long pol_ef = mk_policy_ef();
    const float M = (float)(HW - 4);   // 2044

    // Two points' coords in one 16B load: (x0, y0, x1, y1)
    float4 cxy = ldg_stream4(coords + (size_t)pbase * 2);

    float c0a = fmodf(cxy.x - 1.0f, M); if (c0a < 0.0f) c0a += M; c0a += 1.0f;
    float c1a = fmodf(cxy.y - 1.0f, M); if (c1a < 0.0f) c1a += M; c1a += 1.0f;
    float c0b = fmodf(cxy.z - 1.0f, M); if (c0b < 0.0f) c0b += M; c0b += 1.0f;
    float c1b = fmodf(cxy.w - 1.0f, M); if (c1b < 0.0f) c1b += M; c1b += 1.0f;

    float f0a = floorf(c0a), f1a = floorf(c1a);
    float f0b = floorf(c0b), f1b = floorf(c1b);
    float d0a = c0a - f0a, d1a = c1a - f1a;
    float d0b = c0b - f0b, d1b = c1b - f1b;
    int i0a = (int)f0a, i1a = (int)f1a;
    int i0b = (int)f0b, i1b = (int)f1b;

    // per-point policy: lower image half pinned, upper half streamed
    unsigned long long polA = (i0a < 1024) ? pol_el : pol_ef;
    unsigned long long polB = (i0b < 1024) ? pol_el : pol_ef;

    const float* pa0 = vis + ((size_t)i0a * HW + i1a) * CCH + j * 4;
    const float* pa1 = pa0 + (size_t)HW * CCH;
    const float* pb0 = vis + ((size_t)i0b * HW + i1b) * CCH + j * 4;
    const float* pb1 = pb0 + (size_t)HW * CCH;

    // ---- 4 gather loads in flight ----
    float4 Aa = ldg_vis(pa0, polA);   // point a: tl/bl half (row i0)
    float4 Ba = ldg_vis(pa1, polA);   // point a: tr/br half (row i0+1)
    float4 Ab = ldg_vis(pb0, polB);
    float4 Bb = ldg_vis(pb1, polB);

    // v = B + d0*(A-B): lanes 0,1 -> mt ; lanes 2,3 -> mb
    float4 va, vb;
    va.x = Ba.x + d0a * (Aa.x - Ba.x);
    va.y = Ba.y + d0a * (Aa.y - Ba.y);
    va.z = Ba.z + d0a * (Aa.z - Ba.z);
    va.w = Ba.w + d0a * (Aa.w - Ba.w);
    vb.x = Bb.x + d0b * (Ab.x - Bb.x);
    vb.y = Bb.y + d0b * (Ab.y - Bb.y);
    vb.z = Bb.z + d0b * (Ab.z - Bb.z);
    vb.w = Bb.w + d0b * (Ab.w - Bb.w);

    // exchange mt <-> mb between lane pairs (xor 2)
    float4 oa, ob;
    oa.x = __shfl_xor_sync(mask, va.x, 2);
    oa.y = __shfl_xor_sync(mask, va.y, 2);
    oa.z = __shfl_xor_sync(mask, va.z, 2);
    oa.w = __shfl_xor_sync(mask, va.w, 2);
    ob.x = __shfl_xor_sync(mask, vb.x, 2);
    ob.y = __shfl_xor_sync(mask, vb.y, 2);
    ob.z = __shfl_xor_sync(mask, vb.z, 2);
    ob.w = __shfl_xor_sync(mask, vb.w, 2);

    float4 mta, mba, mtb, mbb;
    if (j < 2) { mta = va; mba = oa; mtb = vb; mbb = ob; }
    else       { mta = oa; mba = va; mtb = ob; mbb = vb; }

    float4 ra, rb;
    ra.x = mba.x + d1a * (mta.x - mba.x);
    ra.y = mba.y + d1a * (mta.y - mba.y);
    ra.z = mba.z + d1a * (mta.z - mba.z);
    ra.w = mba.w + d1a * (mta.w - mba.w);
    rb.x = mbb.x + d1b * (mtb.x - mbb.x);
    rb.y = mbb.y + d1b * (mtb.y - mbb.y);
    rb.z = mbb.z + d1b * (mtb.z - mbb.z);
    rb.w = mbb.w + d1b * (mtb.w - mbb.w);

    // off = c > 2048 never true (c in [1, 2045)): no zeroing.
    if (j < 2) {
        stg_stream4(out + ((size_t)pbase * CCH) + j * 4, ra);
        if (pbase + 1 < n)
            stg_stream4(out + ((size_t)(pbase + 1) * CCH) + j * 4, rb);
    }
}

extern "C" void kernel_launch(void* const* d_in, const int* in_sizes, int n_in,
                              void* d_out, int out_size)
{
    const float* coords = (const float*)d_in[0];
    const float* vis    = (const float*)d_in[1];
    float* out          = (float*)d_out;

    int n = in_sizes[0] / 2;             // number of points
    int threads = 256;                    // 8 warps -> 128 points/block
    int ppb = (threads / 32) * 8 * 2;
    int blocks = (n + ppb - 1) / ppb;
    idx2pixel_pin_kernel<<<blocks, threads>>>(coords, vis, out, n);
}